// round 3
// baseline (speedup 1.0000x reference)
#include <cuda_runtime.h>

// Batched DLT: solve 262144 independent 8x8 systems  h = pinv(A) @ b.
// A is generically nonsingular -> pinv(A)@b == solve(A,b).
// Math in fp64 (matches the fp64 reference); output stored as float32
// (harness __output__ dtype — fp64 stores overflowed the buffer in R0/R1).
//
// Structure (per system, 4 point pairs (u,v) -> (up,vp)):
//   even row p: [0,0,0, -tu,-tv,-1,  cu, cv]  rhs -vp     (tX = trunc, exact)
//   odd  row p: [tu,tv,1, 0, 0, 0, -du,-dv]  rhs  up
// with cu=trunc(vp*u), cv=trunc(vp*v), du=trunc(up*u), dv=trunc(up*v).
// Writing x=h[0:3], y=h[3:6], z=h[6:8], M[p]=(tu_p,tv_p,1):
//   -M y + C z = -vp      M x - D z = up
// Left null vector w of M (cofactors) gives a 2x2 system for z,
// then x,y from a shared 3x3 solve (drop row argmax|w| = natural pivot).

__global__ __launch_bounds__(256)
void dlt_kernel(const float* __restrict__ x, const float* __restrict__ xp,
                float* __restrict__ out, int B)
{
    int i = blockIdx.x * blockDim.x + threadIdx.x;
    if (i >= B) return;

    // Coalesced vector loads: cudaMalloc'd buffers are 16B-aligned.
    float4 a0 = reinterpret_cast<const float4*>(x)[2*i + 0];
    float4 a1 = reinterpret_cast<const float4*>(x)[2*i + 1];
    float4 p0 = reinterpret_cast<const float4*>(xp)[2*i + 0];
    float4 p1 = reinterpret_cast<const float4*>(xp)[2*i + 1];

    double u0 = a0.x, v0 = a0.y, u1 = a0.z, v1 = a0.w;
    double u2 = a1.x, v2 = a1.y, u3 = a1.z, v3 = a1.w;
    double up0 = p0.x, vp0 = p0.y, up1 = p0.z, vp1 = p0.w;
    double up2 = p1.x, vp2 = p1.y, up3 = p1.z, vp3 = p1.w;

    // Truncated (integer-valued) matrix entries — match jnp.trunc in fp64.
    double tu0 = trunc(u0), tu1 = trunc(u1), tu2 = trunc(u2), tu3 = trunc(u3);
    double tv0 = trunc(v0), tv1 = trunc(v1), tv2 = trunc(v2), tv3 = trunc(v3);
    double cu0 = trunc(vp0*u0), cu1 = trunc(vp1*u1), cu2 = trunc(vp2*u2), cu3 = trunc(vp3*u3);
    double cv0 = trunc(vp0*v0), cv1 = trunc(vp1*v1), cv2 = trunc(vp2*v2), cv3 = trunc(vp3*v3);
    double du0 = trunc(up0*u0), du1 = trunc(up1*u1), du2 = trunc(up2*u2), du3 = trunc(up3*u3);
    double dv0 = trunc(up0*v0), dv1 = trunc(up1*v1), dv2 = trunc(up2*v2), dv3 = trunc(up3*v3);

    // Pairwise 2x2 dets of (tu,tv) rows.
    double D01 = tu0*tv1 - tu1*tv0;
    double D02 = tu0*tv2 - tu2*tv0;
    double D03 = tu0*tv3 - tu3*tv0;
    double D12 = tu1*tv2 - tu2*tv1;
    double D13 = tu1*tv3 - tu3*tv1;
    double D23 = tu2*tv3 - tu3*tv2;

    // w^T M = 0 (signed 3x3 cofactor minors, last column all ones).
    double w0 = D12 + D23 - D13;
    double w1 = D03 - D02 - D23;
    double w2 = D01 + D13 - D03;
    double w3 = D02 - D01 - D12;

    // 2x2 system for z = (h7,h8):
    //   (w.cu) z1 + (w.cv) z2 = -(w.vp)
    //   (w.du) z1 + (w.dv) z2 = -(w.up)
    double a11 = w0*cu0 + w1*cu1 + w2*cu2 + w3*cu3;
    double a12 = w0*cv0 + w1*cv1 + w2*cv2 + w3*cv3;
    double a21 = w0*du0 + w1*du1 + w2*du2 + w3*du3;
    double a22 = w0*dv0 + w1*dv1 + w2*dv2 + w3*dv3;
    double b1  = -(w0*vp0 + w1*vp1 + w2*vp2 + w3*vp3);
    double b2  = -(w0*up0 + w1*up1 + w2*up2 + w3*up3);

    double inv2 = 1.0 / (a11*a22 - a12*a21);
    double z1 = (b1*a22 - a12*b2) * inv2;
    double z2 = (a11*b2 - b1*a21) * inv2;

    // RHS for the two 3x3 solves:  M x = up + D z,   M y = vp + C z.
    double gx0 = up0 + du0*z1 + dv0*z2;
    double gx1 = up1 + du1*z1 + dv1*z2;
    double gx2 = up2 + du2*z1 + dv2*z2;
    double gx3 = up3 + du3*z1 + dv3*z2;
    double gy0 = vp0 + cu0*z1 + cv0*z2;
    double gy1 = vp1 + cu1*z1 + cv1*z2;
    double gy2 = vp2 + cu2*z1 + cv2*z2;
    double gy3 = vp3 + cu3*z1 + cv3*z2;

    // Drop the row with max |w| (its 3x3 minor — the retained system's det —
    // is the largest: built-in pivoting). The 4 equations are consistent.
    double aw0 = fabs(w0), aw1 = fabs(w1), aw2 = fabs(w2), aw3 = fabs(w3);
    int k = 0; double awm = aw0;
    if (aw1 > awm) { k = 1; awm = aw1; }
    if (aw2 > awm) { k = 2; awm = aw2; }
    if (aw3 > awm) { k = 3; awm = aw3; }

    // Retained slots: s0 = (k==0)?1:0, s1 = (k<=1)?2:1, s2 = (k<=2)?3:2.
    // Each slot has only two candidates -> one select per scalar.
    bool c0 = (k == 0), c1 = (k <= 1), c2 = (k <= 2);
    double A1 = c0 ? tu1 : tu0,  B1 = c0 ? tv1 : tv0;
    double G1x = c0 ? gx1 : gx0, G1y = c0 ? gy1 : gy0;
    double A2 = c1 ? tu2 : tu1,  B2 = c1 ? tv2 : tv1;
    double G2x = c1 ? gx2 : gx1, G2y = c1 ? gy2 : gy1;
    double A3 = c2 ? tu3 : tu2,  B3 = c2 ? tv3 : tv2;
    double G3x = c2 ? gx3 : gx2, G3y = c2 ? gy3 : gy2;

    // Shared 3x3 solve via adjugate. Rows: (A_i, B_i, 1).
    double E12 = A1*B2 - A2*B1;
    double E23 = A2*B3 - A3*B2;
    double E31 = A3*B1 - A1*B3;
    double inv3 = 1.0 / (E12 + E23 + E31);

    double r11 = B2 - B3, r12 = B3 - B1, r13 = B1 - B2;
    double r21 = A3 - A2, r22 = A1 - A3, r23 = A2 - A1;

    double x1c = (r11*G1x + r12*G2x + r13*G3x) * inv3;
    double x2c = (r21*G1x + r22*G2x + r23*G3x) * inv3;
    double x3c = (E23*G1x + E31*G2x + E12*G3x) * inv3;
    double y1c = (r11*G1y + r12*G2y + r13*G3y) * inv3;
    double y2c = (r21*G1y + r22*G2y + r23*G3y) * inv3;
    double y3c = (E23*G1y + E31*G2y + E12*G3y) * inv3;

    // Store as float32 (output dtype). 9 scalars per system.
    float* o = out + (size_t)i * 9;
    o[0] = (float)x1c; o[1] = (float)x2c; o[2] = (float)x3c;
    o[3] = (float)y1c; o[4] = (float)y2c; o[5] = (float)y3c;
    o[6] = (float)z1;  o[7] = (float)z2;  o[8] = 1.0f;
}

extern "C" void kernel_launch(void* const* d_in, const int* in_sizes, int n_in,
                              void* d_out, int out_size)
{
    const float* x  = (const float*)d_in[0];
    const float* xp = (const float*)d_in[1];
    float* out = (float*)d_out;
    int B = in_sizes[0] / 8;
    int Bo = out_size / 9;
    if (Bo < B) B = Bo;
    dlt_kernel<<<(B + 255) / 256, 256>>>(x, xp, out, B);
}

// round 4
// speedup vs baseline: 1.2582x; 1.2582x over previous
#include <cuda_runtime.h>

// Batched DLT: 262144 independent 8x8 systems h = pinv(A)@b == solve(A,b).
// Hybrid exact-integer / fp64 formulation to dodge B300's weak fp64 pipe:
//  - all trunc'ed quantities are small integers -> int32/int64 exact paths
//  - pairwise dets, null vector w, 2x2 normal matrix, 3x3 cofactors: exact ints
//  - only the genuinely real-valued chains (products before trunc, b-dots,
//    z solve, g RHS, final 3x3 dots) stay in fp64
//  - divisions: fp32 rcp seed + one fp64 Newton step (1e-14 rel)

__device__ __forceinline__ double fast_drcp(double xx)
{
    double r = (double)__frcp_rn((float)xx);      // ~1e-7 seed, off fp64 pipe
    r = r * (2.0 - xx * r);                       // Newton -> ~1e-14
    return r;
}

__global__ __launch_bounds__(256)
void dlt_kernel(const float* __restrict__ x, const float* __restrict__ xp,
                float* __restrict__ out, int B)
{
    int i = blockIdx.x * blockDim.x + threadIdx.x;
    if (i >= B) return;

    float4 a0 = reinterpret_cast<const float4*>(x)[2*i + 0];
    float4 a1 = reinterpret_cast<const float4*>(x)[2*i + 1];
    float4 p0 = reinterpret_cast<const float4*>(xp)[2*i + 0];
    float4 p1 = reinterpret_cast<const float4*>(xp)[2*i + 1];

    double u0 = a0.x, v0 = a0.y, u1 = a0.z, v1 = a0.w;
    double u2 = a1.x, v2 = a1.y, u3 = a1.z, v3 = a1.w;
    double up0 = p0.x, vp0 = p0.y, up1 = p0.z, vp1 = p0.w;
    double up2 = p1.x, vp2 = p1.y, up3 = p1.z, vp3 = p1.w;

    // trunc of a float value: exact via F2I.F32 (|val| < 2^10).
    int tu0 = (int)a0.x, tv0 = (int)a0.y, tu1 = (int)a0.z, tv1 = (int)a0.w;
    int tu2 = (int)a1.x, tv2 = (int)a1.y, tu3 = (int)a1.z, tv3 = (int)a1.w;

    // trunc(vp*u) etc.: product exact in fp64 (24+24<=53 bits), trunc via F2I.
    // All results are integers with |.| < 2^19.
    int cu0 = (int)(vp0*u0), cu1 = (int)(vp1*u1), cu2 = (int)(vp2*u2), cu3 = (int)(vp3*u3);
    int cv0 = (int)(vp0*v0), cv1 = (int)(vp1*v1), cv2 = (int)(vp2*v2), cv3 = (int)(vp3*v3);
    int du0 = (int)(up0*u0), du1 = (int)(up1*u1), du2 = (int)(up2*u2), du3 = (int)(up3*u3);
    int dv0 = (int)(up0*v0), dv1 = (int)(up1*v1), dv2 = (int)(up2*v2), dv3 = (int)(up3*v3);

    // Pairwise 2x2 dets of (tu,tv) rows — exact int32 (< 2^21).
    int D01 = tu0*tv1 - tu1*tv0;
    int D02 = tu0*tv2 - tu2*tv0;
    int D03 = tu0*tv3 - tu3*tv0;
    int D12 = tu1*tv2 - tu2*tv1;
    int D13 = tu1*tv3 - tu3*tv1;
    int D23 = tu2*tv3 - tu3*tv2;

    // Left null vector of M (rows (tu,tv,1)) — exact int32 (< 2^22).
    int w0 = D12 + D23 - D13;
    int w1 = D03 - D02 - D23;
    int w2 = D01 + D13 - D03;
    int w3 = D02 - D01 - D12;

    // 2x2 system for z=(h7,h8): A-entries exact in int64 (|prod|<2^41, sum<2^43).
    long long a11 = (long long)w0*cu0 + (long long)w1*cu1 + (long long)w2*cu2 + (long long)w3*cu3;
    long long a12 = (long long)w0*cv0 + (long long)w1*cv1 + (long long)w2*cv2 + (long long)w3*cv3;
    long long a21 = (long long)w0*du0 + (long long)w1*du1 + (long long)w2*du2 + (long long)w3*du3;
    long long a22 = (long long)w0*dv0 + (long long)w1*dv1 + (long long)w2*dv2 + (long long)w3*dv3;
    double A11 = (double)a11, A12 = (double)a12, A21 = (double)a21, A22 = (double)a22;

    double w0d = (double)w0, w1d = (double)w1, w2d = (double)w2, w3d = (double)w3;
    double b1 = -(w0d*vp0 + w1d*vp1 + w2d*vp2 + w3d*vp3);
    double b2 = -(w0d*up0 + w1d*up1 + w2d*up2 + w3d*up3);

    double inv2 = fast_drcp(A11*A22 - A12*A21);
    double z1 = (b1*A22 - A12*b2) * inv2;
    double z2 = (A11*b2 - b1*A21) * inv2;

    // RHS for the two 3x3 solves: M x = up + D z,  M y = vp + C z.
    double gx0 = up0 + (double)du0*z1 + (double)dv0*z2;
    double gx1 = up1 + (double)du1*z1 + (double)dv1*z2;
    double gx2 = up2 + (double)du2*z1 + (double)dv2*z2;
    double gx3 = up3 + (double)du3*z1 + (double)dv3*z2;
    double gy0 = vp0 + (double)cu0*z1 + (double)cv0*z2;
    double gy1 = vp1 + (double)cu1*z1 + (double)cv1*z2;
    double gy2 = vp2 + (double)cu2*z1 + (double)cv2*z2;
    double gy3 = vp3 + (double)cu3*z1 + (double)cv3*z2;

    // Pivot: drop row argmax|w| (int compares, ALU pipe).
    int aw0 = abs(w0), aw1 = abs(w1), aw2 = abs(w2), aw3 = abs(w3);
    int k = 0, awm = aw0;
    if (aw1 > awm) { k = 1; awm = aw1; }
    if (aw2 > awm) { k = 2; awm = aw2; }
    if (aw3 > awm) { k = 3; awm = aw3; }

    bool c0 = (k == 0), c1 = (k <= 1), c2 = (k <= 2);
    int A1i = c0 ? tu1 : tu0,  B1i = c0 ? tv1 : tv0;
    int A2i = c1 ? tu2 : tu1,  B2i = c1 ? tv2 : tv1;
    int A3i = c2 ? tu3 : tu2,  B3i = c2 ? tv3 : tv2;
    double G1x = c0 ? gx1 : gx0, G1y = c0 ? gy1 : gy0;
    double G2x = c1 ? gx2 : gx1, G2y = c1 ? gy2 : gy1;
    double G3x = c2 ? gx3 : gx2, G3y = c2 ? gy3 : gy2;

    // 3x3 adjugate — all cofactors exact int32.
    int E12 = A1i*B2i - A2i*B1i;
    int E23 = A2i*B3i - A3i*B2i;
    int E31 = A3i*B1i - A1i*B3i;
    int det3 = E12 + E23 + E31;
    double inv3 = fast_drcp((double)det3);

    double r11 = (double)(B2i - B3i), r12 = (double)(B3i - B1i), r13 = (double)(B1i - B2i);
    double r21 = (double)(A3i - A2i), r22 = (double)(A1i - A3i), r23 = (double)(A2i - A1i);
    double e12 = (double)E12, e23 = (double)E23, e31 = (double)E31;

    double x1c = (r11*G1x + r12*G2x + r13*G3x) * inv3;
    double x2c = (r21*G1x + r22*G2x + r23*G3x) * inv3;
    double x3c = (e23*G1x + e31*G2x + e12*G3x) * inv3;
    double y1c = (r11*G1y + r12*G2y + r13*G3y) * inv3;
    double y2c = (r21*G1y + r22*G2y + r23*G3y) * inv3;
    double y3c = (e23*G1y + e31*G2y + e12*G3y) * inv3;

    float* o = out + (size_t)i * 9;
    o[0] = (float)x1c; o[1] = (float)x2c; o[2] = (float)x3c;
    o[3] = (float)y1c; o[4] = (float)y2c; o[5] = (float)y3c;
    o[6] = (float)z1;  o[7] = (float)z2;  o[8] = 1.0f;
}

extern "C" void kernel_launch(void* const* d_in, const int* in_sizes, int n_in,
                              void* d_out, int out_size)
{
    const float* x  = (const float*)d_in[0];
    const float* xp = (const float*)d_in[1];
    float* out = (float*)d_out;
    int B = in_sizes[0] / 8;
    int Bo = out_size / 9;
    if (Bo < B) B = Bo;
    dlt_kernel<<<(B + 255) / 256, 256>>>(x, xp, out, B);
}

// round 5
// speedup vs baseline: 2.8322x; 2.2509x over previous
#include <cuda_runtime.h>

// Batched DLT: 262144 independent 8x8 systems, h = pinv(A)@b == solve(A,b).
// R5: move the entire real-valued chain off B300's slashed fp64 pipe onto
// double-single (df64 = hi/lo fp32, eps ~2^-44) on the fp32 FFMA pipe (27x
// the fp64 throughput). Only the 16 products feeding trunc stay fp64 (exact,
// and trunc is discontinuous so they must be bit-identical to the reference).
// Integer skeleton (pairwise dets, null vector w, 2x2 normal matrix entries,
// 3x3 cofactors) is exact int32/int64 as in R4.

struct df { float h, l; };

__device__ __forceinline__ float2 two_sum(float a, float b) {
    float s = a + b; float bb = s - a;
    float e = (a - (s - bb)) + (b - bb);
    return make_float2(s, e);
}
__device__ __forceinline__ df qts(float a, float b) {   // |a| >= |b|
    float s = a + b; float e = b - (s - a);
    return df{s, e};
}
__device__ __forceinline__ df df_add(df x, df y) {
    float2 s = two_sum(x.h, y.h);
    s.y += x.l + y.l;
    return qts(s.x, s.y);
}
__device__ __forceinline__ df df_sub(df x, df y) {
    return df_add(x, df{-y.h, -y.l});
}
__device__ __forceinline__ df df_mul(df x, df y) {
    float p = x.h * y.h;
    float e = fmaf(x.h, y.h, -p);
    e += fmaf(x.h, y.l, x.l * y.h);
    return qts(p, e);
}
__device__ __forceinline__ df df_smul(float s, df x) {   // scalar * df
    float p = s * x.h;
    float e = fmaf(s, x.h, -p);
    e = fmaf(s, x.l, e);
    return qts(p, e);
}
__device__ __forceinline__ df df_prod(float a, float b) { // exact a*b as df
    float p = a * b;
    float e = fmaf(a, b, -p);
    return df{p, e};
}
__device__ __forceinline__ df df_adds(df x, float s) {
    float2 t = two_sum(x.h, s);
    t.y += x.l;
    return qts(t.x, t.y);
}
__device__ __forceinline__ df df_from_ll(long long v) {  // exact for |v|<2^48
    float h = (float)v;
    float l = (float)(v - (long long)h);
    return df{h, l};
}
__device__ __forceinline__ df df_recip(df x) {           // ~2^-44 rel
    float r0 = __frcp_rn(x.h);
    float e = fmaf(x.h, r0, -1.0f);
    e = fmaf(x.l, r0, e);
    return qts(r0, -r0 * e);
}
__device__ __forceinline__ df df_recip_s(float d) {
    float r0 = __frcp_rn(d);
    float e = fmaf(d, r0, -1.0f);
    return qts(r0, -r0 * e);
}
__device__ __forceinline__ float df_mul_to_f(df x, df y) {
    float t = fmaf(x.h, y.l, x.l * y.h);
    return fmaf(x.h, y.h, t);
}

__global__ __launch_bounds__(256)
void dlt_kernel(const float* __restrict__ x, const float* __restrict__ xp,
                float* __restrict__ out, int B)
{
    int i = blockIdx.x * blockDim.x + threadIdx.x;
    if (i >= B) return;

    float4 a0 = reinterpret_cast<const float4*>(x)[2*i + 0];
    float4 a1 = reinterpret_cast<const float4*>(x)[2*i + 1];
    float4 p0 = reinterpret_cast<const float4*>(xp)[2*i + 0];
    float4 p1 = reinterpret_cast<const float4*>(xp)[2*i + 1];

    float u0f = a0.x, v0f = a0.y, u1f = a0.z, v1f = a0.w;
    float u2f = a1.x, v2f = a1.y, u3f = a1.z, v3f = a1.w;
    float up0f = p0.x, vp0f = p0.y, up1f = p0.z, vp1f = p0.w;
    float up2f = p1.x, vp2f = p1.y, up3f = p1.z, vp3f = p1.w;

    // trunc of raw float coordinates: exact via F2I (|val| < 2^12).
    int tu0 = (int)u0f, tv0 = (int)v0f, tu1 = (int)u1f, tv1 = (int)v1f;
    int tu2 = (int)u2f, tv2 = (int)v2f, tu3 = (int)u3f, tv3 = (int)v3f;

    // trunc(vp*u) etc.: product MUST be exact -> fp64 mul (24+24 <= 53 bits),
    // then exact F2I.F64 trunc. These 16 DMULs are the only fp64 ops left,
    // and they overlap with the fp32 stream below.
    double u0 = u0f, v0 = v0f, u1 = u1f, v1 = v1f;
    double u2 = u2f, v2 = v2f, u3 = u3f, v3 = v3f;
    double up0 = up0f, vp0 = vp0f, up1 = up1f, vp1 = vp1f;
    double up2 = up2f, vp2 = vp2f, up3 = up3f, vp3 = vp3f;
    int cu0 = (int)(vp0*u0), cu1 = (int)(vp1*u1), cu2 = (int)(vp2*u2), cu3 = (int)(vp3*u3);
    int cv0 = (int)(vp0*v0), cv1 = (int)(vp1*v1), cv2 = (int)(vp2*v2), cv3 = (int)(vp3*v3);
    int du0 = (int)(up0*u0), du1 = (int)(up1*u1), du2 = (int)(up2*u2), du3 = (int)(up3*u3);
    int dv0 = (int)(up0*v0), dv1 = (int)(up1*v1), dv2 = (int)(up2*v2), dv3 = (int)(up3*v3);

    // Pairwise dets + left null vector w of M — exact int32.
    int D01 = tu0*tv1 - tu1*tv0;
    int D02 = tu0*tv2 - tu2*tv0;
    int D03 = tu0*tv3 - tu3*tv0;
    int D12 = tu1*tv2 - tu2*tv1;
    int D13 = tu1*tv3 - tu3*tv1;
    int D23 = tu2*tv3 - tu3*tv2;
    int w0 = D12 + D23 - D13;
    int w1 = D03 - D02 - D23;
    int w2 = D01 + D13 - D03;
    int w3 = D02 - D01 - D12;

    // 2x2 normal-matrix entries — exact int64 (|.| < 2^43).
    long long a11 = (long long)w0*cu0 + (long long)w1*cu1 + (long long)w2*cu2 + (long long)w3*cu3;
    long long a12 = (long long)w0*cv0 + (long long)w1*cv1 + (long long)w2*cv2 + (long long)w3*cv3;
    long long a21 = (long long)w0*du0 + (long long)w1*du1 + (long long)w2*du2 + (long long)w3*du3;
    long long a22 = (long long)w0*dv0 + (long long)w1*dv1 + (long long)w2*dv2 + (long long)w3*dv3;
    df A11 = df_from_ll(a11), A12 = df_from_ll(a12);
    df A21 = df_from_ll(a21), A22 = df_from_ll(a22);

    // b1 = -(w . vp), b2 = -(w . up): w exact in fp32 (|w| < 2^23).
    float w0f = (float)w0, w1f = (float)w1, w2f = (float)w2, w3f = (float)w3;
    df b1 = df_add(df_add(df_prod(-w0f, vp0f), df_prod(-w1f, vp1f)),
                   df_add(df_prod(-w2f, vp2f), df_prod(-w3f, vp3f)));
    df b2 = df_add(df_add(df_prod(-w0f, up0f), df_prod(-w1f, up1f)),
                   df_add(df_prod(-w2f, up2f), df_prod(-w3f, up3f)));

    // z = (h7,h8) via Cramer on the 2x2.
    df det2 = df_sub(df_mul(A11, A22), df_mul(A12, A21));
    df inv2 = df_recip(det2);
    df z1 = df_mul(df_sub(df_mul(b1, A22), df_mul(A12, b2)), inv2);
    df z2 = df_mul(df_sub(df_mul(A11, b2), df_mul(b1, A21)), inv2);

    // RHS of the two 3x3 solves: gx = up + D z, gy = vp + C z.
    float du0f=(float)du0, du1f=(float)du1, du2f=(float)du2, du3f=(float)du3;
    float dv0f=(float)dv0, dv1f=(float)dv1, dv2f=(float)dv2, dv3f=(float)dv3;
    float cu0f=(float)cu0, cu1f=(float)cu1, cu2f=(float)cu2, cu3f=(float)cu3;
    float cv0f=(float)cv0, cv1f=(float)cv1, cv2f=(float)cv2, cv3f=(float)cv3;

    df gx0 = df_adds(df_add(df_smul(du0f, z1), df_smul(dv0f, z2)), up0f);
    df gx1 = df_adds(df_add(df_smul(du1f, z1), df_smul(dv1f, z2)), up1f);
    df gx2 = df_adds(df_add(df_smul(du2f, z1), df_smul(dv2f, z2)), up2f);
    df gx3 = df_adds(df_add(df_smul(du3f, z1), df_smul(dv3f, z2)), up3f);
    df gy0 = df_adds(df_add(df_smul(cu0f, z1), df_smul(cv0f, z2)), vp0f);
    df gy1 = df_adds(df_add(df_smul(cu1f, z1), df_smul(cv1f, z2)), vp1f);
    df gy2 = df_adds(df_add(df_smul(cu2f, z1), df_smul(cv2f, z2)), vp2f);
    df gy3 = df_adds(df_add(df_smul(cu3f, z1), df_smul(cv3f, z2)), vp3f);

    // Pivot: drop row argmax|w| (ALU pipe).
    int aw0 = abs(w0), aw1 = abs(w1), aw2 = abs(w2), aw3 = abs(w3);
    int k = 0, awm = aw0;
    if (aw1 > awm) { k = 1; awm = aw1; }
    if (aw2 > awm) { k = 2; awm = aw2; }
    if (aw3 > awm) { k = 3; awm = aw3; }
    bool c0 = (k == 0), c1 = (k <= 1), c2 = (k <= 2);

    int A1i = c0 ? tu1 : tu0,  B1i = c0 ? tv1 : tv0;
    int A2i = c1 ? tu2 : tu1,  B2i = c1 ? tv2 : tv1;
    int A3i = c2 ? tu3 : tu2,  B3i = c2 ? tv3 : tv2;
    df G1x = c0 ? gx1 : gx0, G1y = c0 ? gy1 : gy0;
    df G2x = c1 ? gx2 : gx1, G2y = c1 ? gy2 : gy1;
    df G3x = c2 ? gx3 : gx2, G3y = c2 ? gy3 : gy2;

    // 3x3 adjugate — exact int32, exact in fp32 (< 2^22).
    int E12 = A1i*B2i - A2i*B1i;
    int E23 = A2i*B3i - A3i*B2i;
    int E31 = A3i*B1i - A1i*B3i;
    int det3 = E12 + E23 + E31;
    df inv3 = df_recip_s((float)det3);

    float r11 = (float)(B2i - B3i), r12 = (float)(B3i - B1i), r13 = (float)(B1i - B2i);
    float r21 = (float)(A3i - A2i), r22 = (float)(A1i - A3i), r23 = (float)(A2i - A1i);
    float e12 = (float)E12, e23 = (float)E23, e31 = (float)E31;

    df sx1 = df_add(df_smul(r11, G1x), df_add(df_smul(r12, G2x), df_smul(r13, G3x)));
    df sx2 = df_add(df_smul(r21, G1x), df_add(df_smul(r22, G2x), df_smul(r23, G3x)));
    df sx3 = df_add(df_smul(e23, G1x), df_add(df_smul(e31, G2x), df_smul(e12, G3x)));
    df sy1 = df_add(df_smul(r11, G1y), df_add(df_smul(r12, G2y), df_smul(r13, G3y)));
    df sy2 = df_add(df_smul(r21, G1y), df_add(df_smul(r22, G2y), df_smul(r23, G3y)));
    df sy3 = df_add(df_smul(e23, G1y), df_add(df_smul(e31, G2y), df_smul(e12, G3y)));

    float* o = out + (size_t)i * 9;
    o[0] = df_mul_to_f(sx1, inv3);
    o[1] = df_mul_to_f(sx2, inv3);
    o[2] = df_mul_to_f(sx3, inv3);
    o[3] = df_mul_to_f(sy1, inv3);
    o[4] = df_mul_to_f(sy2, inv3);
    o[5] = df_mul_to_f(sy3, inv3);
    o[6] = z1.h + z1.l;
    o[7] = z2.h + z2.l;
    o[8] = 1.0f;
}

extern "C" void kernel_launch(void* const* d_in, const int* in_sizes, int n_in,
                              void* d_out, int out_size)
{
    const float* x  = (const float*)d_in[0];
    const float* xp = (const float*)d_in[1];
    float* out = (float*)d_out;
    int B = in_sizes[0] / 8;
    int Bo = out_size / 9;
    if (Bo < B) B = Bo;
    dlt_kernel<<<(B + 255) / 256, 256>>>(x, xp, out, B);
}

// round 6
// speedup vs baseline: 7.1086x; 2.5100x over previous
#include <cuda_runtime.h>

// Batched DLT: 262144 independent 8x8 systems, h = pinv(A)@b == solve(A,b).
// R6: zero fp64. Exact trunc of fp32*fp32 products via df split + sign fix.
// df64 (hi/lo fp32) kept only for the cancellation-sensitive z-chain
// (b-dots, 2x2 normal matrix det, Cramer). Everything downstream (gx/gy RHS,
// 3x3 adjugate solve) is plain fp32 — amplification keeps error ~1e-6,
// 1000x under the 1e-3 gate. Integer skeleton exact as before.

struct df { float h, l; };

__device__ __forceinline__ float2 two_sum(float a, float b) {
    float s = a + b; float bb = s - a;
    float e = (a - (s - bb)) + (b - bb);
    return make_float2(s, e);
}
__device__ __forceinline__ df qts(float a, float b) {   // |a| >= |b|
    float s = a + b; float e = b - (s - a);
    return df{s, e};
}
__device__ __forceinline__ df df_add(df x, df y) {
    float2 s = two_sum(x.h, y.h);
    s.y += x.l + y.l;
    return qts(s.x, s.y);
}
__device__ __forceinline__ df df_sub(df x, df y) {
    return df_add(x, df{-y.h, -y.l});
}
__device__ __forceinline__ df df_mul(df x, df y) {
    float p = x.h * y.h;
    float e = fmaf(x.h, y.h, -p);
    e += fmaf(x.h, y.l, x.l * y.h);
    return qts(p, e);
}
__device__ __forceinline__ df df_prod(float a, float b) { // exact a*b
    float p = a * b;
    float e = fmaf(a, b, -p);
    return df{p, e};
}
__device__ __forceinline__ df df_from_ll(long long v) {  // exact for |v|<2^48
    float h = (float)v;
    float l = (float)(v - (long long)h);
    return df{h, l};
}
__device__ __forceinline__ df df_recip(df x) {
    float r0 = __frcp_rn(x.h);
    float e = fmaf(x.h, r0, -1.0f);
    e = fmaf(x.l, r0, e);
    return qts(r0, -r0 * e);
}

// Exact trunc(a*b) matching fp64 semantics: V = p + e is the exact product.
// frac = p - trunc(p) is a multiple of ulp(p) and |e| <= ulp(p)/2, so
// frac != 0 never flips sign of (frac + e); only frac == 0 needs the fix.
__device__ __forceinline__ int trunc_prod(float a, float b) {
    float p = a * b;
    float e = fmaf(a, b, -p);
    int it = (int)p;                 // F2I trunc of hi part
    float t = (float)it;
    float d = (p - t) + e;           // exact frac + exact err
    if (d < 0.0f && it > 0) it -= 1; // V just below integer p
    if (d > 0.0f && it < 0) it += 1; // V just above integer p (negative side)
    return it;
}

__global__ __launch_bounds__(256, 4)
void dlt_kernel(const float* __restrict__ x, const float* __restrict__ xp,
                float* __restrict__ out, int B)
{
    int i = blockIdx.x * blockDim.x + threadIdx.x;
    if (i >= B) return;

    float4 a0 = reinterpret_cast<const float4*>(x)[2*i + 0];
    float4 a1 = reinterpret_cast<const float4*>(x)[2*i + 1];
    float4 p0 = reinterpret_cast<const float4*>(xp)[2*i + 0];
    float4 p1 = reinterpret_cast<const float4*>(xp)[2*i + 1];

    float u0 = a0.x, v0 = a0.y, u1 = a0.z, v1 = a0.w;
    float u2 = a1.x, v2 = a1.y, u3 = a1.z, v3 = a1.w;
    float up0 = p0.x, vp0 = p0.y, up1 = p0.z, vp1 = p0.w;
    float up2 = p1.x, vp2 = p1.y, up3 = p1.z, vp3 = p1.w;

    // trunc of raw coordinates: exact F2I.
    int tu0 = (int)u0, tv0 = (int)v0, tu1 = (int)u1, tv1 = (int)v1;
    int tu2 = (int)u2, tv2 = (int)v2, tu3 = (int)u3, tv3 = (int)v3;

    // trunc(vp*u) etc. — exact, no fp64. 16 independent short chains.
    int cu0 = trunc_prod(vp0, u0), cu1 = trunc_prod(vp1, u1);
    int cu2 = trunc_prod(vp2, u2), cu3 = trunc_prod(vp3, u3);
    int cv0 = trunc_prod(vp0, v0), cv1 = trunc_prod(vp1, v1);
    int cv2 = trunc_prod(vp2, v2), cv3 = trunc_prod(vp3, v3);
    int du0 = trunc_prod(up0, u0), du1 = trunc_prod(up1, u1);
    int du2 = trunc_prod(up2, u2), du3 = trunc_prod(up3, u3);
    int dv0 = trunc_prod(up0, v0), dv1 = trunc_prod(up1, v1);
    int dv2 = trunc_prod(up2, v2), dv3 = trunc_prod(up3, v3);

    // Pairwise dets + left null vector w of M — exact int32.
    int D01 = tu0*tv1 - tu1*tv0;
    int D02 = tu0*tv2 - tu2*tv0;
    int D03 = tu0*tv3 - tu3*tv0;
    int D12 = tu1*tv2 - tu2*tv1;
    int D13 = tu1*tv3 - tu3*tv1;
    int D23 = tu2*tv3 - tu3*tv2;
    int w0 = D12 + D23 - D13;
    int w1 = D03 - D02 - D23;
    int w2 = D01 + D13 - D03;
    int w3 = D02 - D01 - D12;

    // 2x2 normal-matrix entries — exact int64 (|.| < 2^43).
    long long a11 = (long long)w0*cu0 + (long long)w1*cu1 + (long long)w2*cu2 + (long long)w3*cu3;
    long long a12 = (long long)w0*cv0 + (long long)w1*cv1 + (long long)w2*cv2 + (long long)w3*cv3;
    long long a21 = (long long)w0*du0 + (long long)w1*du1 + (long long)w2*du2 + (long long)w3*du3;
    long long a22 = (long long)w0*dv0 + (long long)w1*dv1 + (long long)w2*dv2 + (long long)w3*dv3;
    df A11 = df_from_ll(a11), A12 = df_from_ll(a12);
    df A21 = df_from_ll(a21), A22 = df_from_ll(a22);

    // b1 = -(w . vp), b2 = -(w . up): w exact in fp32 (|w| < 2^23).
    float w0f = (float)w0, w1f = (float)w1, w2f = (float)w2, w3f = (float)w3;
    df b1 = df_add(df_add(df_prod(-w0f, vp0), df_prod(-w1f, vp1)),
                   df_add(df_prod(-w2f, vp2), df_prod(-w3f, vp3)));
    df b2 = df_add(df_add(df_prod(-w0f, up0), df_prod(-w1f, up1)),
                   df_add(df_prod(-w2f, up2), df_prod(-w3f, up3)));

    // z = (h7,h8) via Cramer on the 2x2 (df for cancellation safety).
    df det2 = df_sub(df_mul(A11, A22), df_mul(A12, A21));
    df inv2 = df_recip(det2);
    df z1d = df_mul(df_sub(df_mul(b1, A22), df_mul(A12, b2)), inv2);
    df z2d = df_mul(df_sub(df_mul(A11, b2), df_mul(b1, A21)), inv2);
    float z1 = z1d.h + z1d.l;
    float z2 = z2d.h + z2d.l;

    // RHS of the two 3x3 solves — plain fp32 (amplification analysis: ~1e-6).
    float gx0 = fmaf((float)du0, z1, fmaf((float)dv0, z2, up0));
    float gx1 = fmaf((float)du1, z1, fmaf((float)dv1, z2, up1));
    float gx2 = fmaf((float)du2, z1, fmaf((float)dv2, z2, up2));
    float gx3 = fmaf((float)du3, z1, fmaf((float)dv3, z2, up3));
    float gy0 = fmaf((float)cu0, z1, fmaf((float)cv0, z2, vp0));
    float gy1 = fmaf((float)cu1, z1, fmaf((float)cv1, z2, vp1));
    float gy2 = fmaf((float)cu2, z1, fmaf((float)cv2, z2, vp2));
    float gy3 = fmaf((float)cu3, z1, fmaf((float)cv3, z2, vp3));

    // Pivot: drop row argmax|w| (the retained 3x3's det is the largest minor).
    int aw0 = abs(w0), aw1 = abs(w1), aw2 = abs(w2), aw3 = abs(w3);
    int k = 0, awm = aw0;
    if (aw1 > awm) { k = 1; awm = aw1; }
    if (aw2 > awm) { k = 2; awm = aw2; }
    if (aw3 > awm) { k = 3; awm = aw3; }
    bool c0 = (k == 0), c1 = (k <= 1), c2 = (k <= 2);

    int A1i = c0 ? tu1 : tu0,  B1i = c0 ? tv1 : tv0;
    int A2i = c1 ? tu2 : tu1,  B2i = c1 ? tv2 : tv1;
    int A3i = c2 ? tu3 : tu2,  B3i = c2 ? tv3 : tv2;
    float G1x = c0 ? gx1 : gx0, G1y = c0 ? gy1 : gy0;
    float G2x = c1 ? gx2 : gx1, G2y = c1 ? gy2 : gy1;
    float G3x = c2 ? gx3 : gx2, G3y = c2 ? gy3 : gy2;

    // 3x3 adjugate — exact int32, then fp32 solve.
    int E12 = A1i*B2i - A2i*B1i;
    int E23 = A2i*B3i - A3i*B2i;
    int E31 = A3i*B1i - A1i*B3i;
    int det3 = E12 + E23 + E31;
    float inv3 = __frcp_rn((float)det3);

    float r11 = (float)(B2i - B3i), r12 = (float)(B3i - B1i), r13 = (float)(B1i - B2i);
    float r21 = (float)(A3i - A2i), r22 = (float)(A1i - A3i), r23 = (float)(A2i - A1i);
    float e12 = (float)E12, e23 = (float)E23, e31 = (float)E31;

    float x1c = fmaf(r11, G1x, fmaf(r12, G2x, r13 * G3x)) * inv3;
    float x2c = fmaf(r21, G1x, fmaf(r22, G2x, r23 * G3x)) * inv3;
    float x3c = fmaf(e23, G1x, fmaf(e31, G2x, e12 * G3x)) * inv3;
    float y1c = fmaf(r11, G1y, fmaf(r12, G2y, r13 * G3y)) * inv3;
    float y2c = fmaf(r21, G1y, fmaf(r22, G2y, r23 * G3y)) * inv3;
    float y3c = fmaf(e23, G1y, fmaf(e31, G2y, e12 * G3y)) * inv3;

    float* o = out + (size_t)i * 9;
    o[0] = x1c; o[1] = x2c; o[2] = x3c;
    o[3] = y1c; o[4] = y2c; o[5] = y3c;
    o[6] = z1;  o[7] = z2;  o[8] = 1.0f;
}

extern "C" void kernel_launch(void* const* d_in, const int* in_sizes, int n_in,
                              void* d_out, int out_size)
{
    const float* x  = (const float*)d_in[0];
    const float* xp = (const float*)d_in[1];
    float* out = (float*)d_out;
    int B = in_sizes[0] / 8;
    int Bo = out_size / 9;
    if (Bo < B) B = Bo;
    dlt_kernel<<<(B + 255) / 256, 256>>>(x, xp, out, B);
}